// round 14
// baseline (speedup 1.0000x reference)
#include <cuda_runtime.h>
#include <cuda_bf16.h>
#include <cstdint>

#define FF 481
#define KK 48
#define TT 1024
#define BB 4
#define FPC 8            // frames per CTA (8 warps; Phase A: warp <-> frame)
#define NTH 256
#define KC 64            // f per chunk
#define NCHUNK 8
#define KPAD 512         // 8 * 64

// smem byte offsets. A/B tiles row stride 72 bf16 = 144 B (ldmatrix conflict-free).
#define OFF_AH   0               // 128 x 72 bf16 = 18432
#define OFF_AL   18432
#define OFF_B0H  36864           // 96 x 72 bf16 = 13824
#define OFF_B0L  50688
#define OFF_B1H  64512
#define OFF_B1L  78336
#define OFF_XS   92160           // 64 rows x 76 floats (304 B) = 19456
#define OFF_C2   111616          // 512 floats = 2048
#define SMEM_BYTES 113664
#define OFF_DSM  0               // epilogue alias: 128*97 floats = 49664 B

__device__ float g_invds[KK];
__device__ __align__(16) __nv_bfloat16 g_Bh[96 * KPAD];
__device__ __align__(16) __nv_bfloat16 g_Bl[96 * KPAD];

// ---------------------------------------------------------------------------
__device__ __forceinline__ float frsqrt_a(float x) {
    float r; asm("rsqrt.approx.f32 %0, %1;" : "=f"(r) : "f"(x)); return r;
}
__device__ __forceinline__ float frcp_a(float x) {
    float r; asm("rcp.approx.f32 %0, %1;" : "=f"(r) : "f"(x)); return r;
}
__device__ __forceinline__ uint32_t smem_u32(const void* p) {
    uint32_t a;
    asm("{ .reg .u64 t; cvta.to.shared.u64 t, %1; cvt.u32.u64 %0, t; }" : "=r"(a) : "l"(p));
    return a;
}

#define CP16(dst, src) asm volatile("cp.async.cg.shared.global [%0], [%1], 16;" :: "r"(dst), "l"(src))
#define CP_COMMIT()    asm volatile("cp.async.commit_group;" ::: "memory")
#define CP_WAIT0()     asm volatile("cp.async.wait_group 0;" ::: "memory")
#define STSF(addr, v)  asm volatile("st.shared.f32 [%0], %1;" :: "r"(addr), "f"(v))

#define LDSM4(r, a)                                                          \
    asm volatile("ldmatrix.sync.aligned.m8n8.x4.shared.b16 {%0,%1,%2,%3}, [%4];" \
        : "=r"((r)[0]), "=r"((r)[1]), "=r"((r)[2]), "=r"((r)[3]) : "r"(a))

#define MMA16816(c, a, b0, b1)                                               \
    asm volatile("mma.sync.aligned.m16n8k16.row.col.f32.bf16.bf16.f32 "      \
        "{%0,%1,%2,%3}, {%4,%5,%6,%7}, {%8,%9}, {%0,%1,%2,%3};"              \
        : "+f"((c)[0]), "+f"((c)[1]), "+f"((c)[2]), "+f"((c)[3])             \
        : "r"((a)[0]), "r"((a)[1]), "r"((a)[2]), "r"((a)[3]),                \
          "r"(b0), "r"(b1))

// ---------------------------------------------------------------------------
// Prep (merged): blocks [0,192): band -> bf16 hi/lo [96 n][KPAD];
// blocks [192,240): invds[k] = 1 / sum_f band_re[f,k].
__global__ void pv_prep(const float* __restrict__ band_re,
                        const float* __restrict__ band_im)
{
    if (blockIdx.x < 192) {
        const int idx = blockIdx.x * 256 + threadIdx.x;   // < 96*512
        const int n = idx >> 9, f = idx & (KPAD - 1);
        float v = 0.f;
        if (f < FF) v = (n < KK) ? band_re[f * KK + n] : band_im[f * KK + (n - KK)];
        const __nv_bfloat16 h = __float2bfloat16(v);
        g_Bh[idx] = h;
        g_Bl[idx] = __float2bfloat16(v - __bfloat162float(h));
    } else {
        const int k = blockIdx.x - 192;
        float s = 0.f;
        for (int f = threadIdx.x; f < FF; f += 256) s += band_re[f * KK + k];
        __shared__ float red[8];
        #pragma unroll
        for (int o = 16; o; o >>= 1) s += __shfl_xor_sync(0xffffffffu, s, o);
        if ((threadIdx.x & 31) == 0) red[threadIdx.x >> 5] = s;
        __syncthreads();
        if (threadIdx.x == 0) {
            float t = 0.f;
            #pragma unroll
            for (int i = 0; i < 8; i++) t += red[i];
            g_invds[k] = 1.0f / fmaxf(t, 1e-20f);
        }
    }
}

// ---------------------------------------------------------------------------
// Stage this warp's 8 bins rows for chunk starting at f0 into its private xs
// slab via 16B cp.async (aligned-down; per-row delta packed into return).
// Garbage in slots outside [delta, delta+L) is never read by the consumer.
// edgeLow/edgeHigh: the two rows that could touch outside the allocation take
// a clamped scalar path.
__device__ __forceinline__ uint32_t stage_xs(uint32_t sb, int wid, int lid,
                                             const float* __restrict__ reB,
                                             const float* __restrict__ imB,
                                             int f0, bool edgeLow, bool edgeHigh)
{
    const int wstart = (f0 == 0) ? 0 : f0 - 1;
    int wlast = f0 + 64; if (wlast > FF - 1) wlast = FF - 1;
    const int L = wlast - wstart + 1;
    uint32_t dpack = 0;
    #pragma unroll
    for (int r = 0; r < 8; r++) {
        const int ch = r >> 1, im = r & 1;
        const float* Gr = (im ? imB : reB) + ch * FF;
        const float* A = Gr + wstart;
        const uint32_t delta = ((uint32_t)(uintptr_t)A >> 2) & 3u;
        dpack |= delta << (r * 4);
        const float* Aal = A - (int)delta;
        const int n4 = (L + (int)delta + 3) >> 2;
        const uint32_t dst = sb + OFF_XS + (wid * 8 + r) * 304;
        const bool danger = (edgeLow && r == 0) || (edgeHigh && r == 7);
        if (!danger) {
            if (lid < n4) CP16(dst + lid * 16, Aal + lid * 4);
        } else {
            for (int s = lid; s < n4 * 4; s += 32) {
                int gidx = wstart - (int)delta + s;
                gidx = gidx < 0 ? 0 : (gidx > FF - 1 ? FF - 1 : gidx);
                STSF(dst + s * 4, Gr[gidx]);
            }
        }
    }
    return dpack;
}

// ---------------------------------------------------------------------------
// Phase A per frequency, reading the warp's xs slab.
__device__ __forceinline__ void phaseA_s(const float* __restrict__ xsw,
                                         uint32_t dpack, int wstart,
                                         int f, float* v)
{
    int fm = f - 1; fm = fm < 0 ? 0 : (fm > FF - 3 ? FF - 3 : fm);
    const int fp = fm + 2;
    const int bx = f - wstart, bm = fm - wstart, bp = fp - wstart;
    float yr[4], yi[4], dv[4];
    float dsum = 0.f;
    #pragma unroll
    for (int ch = 0; ch < 4; ch++) {
        const float* rr = xsw + (ch * 2) * 76;
        const float* ii = xsw + (ch * 2 + 1) * 76;
        const int dre = (dpack >> (ch * 8)) & 15;
        const int dim_ = (dpack >> (ch * 8 + 4)) & 15;
        const float xr = rr[bx + dre], xi = ii[bx + dim_];
        const float mr = rr[bm + dre], mi = ii[bm + dim_];
        const float pr = rr[bp + dre], pi = ii[bp + dim_];
        const float d  = xr * xr + xi * xi;
        const float dm = mr * mr + mi * mi;
        const float dp = pr * pr + pi * pi;
        const float ur = mr * pr + mi * pi;       // conj(x_fm) * x_fp
        const float ui = mr * pi - mi * pr;
        const float s  = d * frsqrt_a(fmaxf(d * dm * dp, 1e-38f)); // = |x_f|/|u|
        yr[ch] = s * ur; yi[ch] = s * ui;
        dv[ch] = d; dsum += d;
    }
    const float invp = frcp_a(fmaxf(dsum, 1e-20f));
    const float l0r = yr[0] * invp, l0i = yi[0] * invp;
    const float l1r = yr[1] * invp, l1i = yi[1] * invp;
    const float l2r = yr[2] * invp, l2i = yi[2] * invp;
    v[0]  = dv[0] * invp;  v[1]  = dv[1] * invp;
    v[2]  = l0r*yr[1] + l0i*yi[1];  v[3]  = l0i*yr[1] - l0r*yi[1];   // v01
    v[4]  = dv[2] * invp;  v[5]  = dv[3] * invp;
    v[6]  = l2r*yr[3] + l2i*yi[3];  v[7]  = l2i*yr[3] - l2r*yi[3];   // v23
    v[8]  = l0r*yr[2] + l0i*yi[2];  v[9]  = l0i*yr[2] - l0r*yi[2];   // v02
    v[10] = l1r*yr[3] + l1i*yi[3];  v[11] = l1i*yr[3] - l1r*yi[3];   // v13
    v[12] = l0r*yr[3] + l0i*yi[3];  v[13] = l0i*yr[3] - l0r*yi[3];   // v03
    v[14] = l1r*yr[2] + l1i*yi[2];  v[15] = l1i*yr[2] - l1r*yi[2];   // v12
}

// B tile prefetcher (warp-cooperative, cp.async 16B)
__device__ __forceinline__ void stage_b(uint32_t sb, int wid, int lid,
                                        uint32_t offH, uint32_t offL, int f0)
{
    #pragma unroll
    for (int it0 = 0; it0 < 96; it0 += 32) {
        const int it = it0 + lid;
        const int row = wid * 12 + (it >> 3), q = it & 7;
        CP16(sb + offH + row * 144 + q * 16, g_Bh + row * KPAD + f0 + q * 8);
        CP16(sb + offL + row * 144 + q * 16, g_Bl + row * KPAD + f0 + q * 8);
    }
}

// ---------------------------------------------------------------------------
__global__ __launch_bounds__(NTH, 2)
void pv_main(const float* __restrict__ bins_re, const float* __restrict__ bins_im,
             const float* __restrict__ c2pv_re, const float* __restrict__ c2pv_im,
             float* __restrict__ out)
{
    extern __shared__ unsigned char smem[];
    float* smf = (float*)smem;
    const uint32_t sb = smem_u32(smem);
    const int tid = threadIdx.x;
    const int wid = tid >> 5;
    const int lid = tid & 31;
    const int b   = blockIdx.y;
    const int t0  = blockIdx.x * FPC;

    float* c2s = smf + OFF_C2 / 4;
    for (int i = tid; i < 256; i += NTH) {
        c2s[i] = c2pv_re[i]; c2s[256 + i] = c2pv_im[i];
    }

    // Phase A source rows for this warp's frame
    const float* reB = bins_re + ((size_t)((b * TT + t0 + wid) * 4)) * FF;
    const float* imB = bins_im + ((size_t)((b * TT + t0 + wid) * 4)) * FF;
    const bool edgeLowW  = (blockIdx.x == 0 && blockIdx.y == 0 && wid == 0);
    const bool edgeHighW = (blockIdx.x == gridDim.x - 1 && blockIdx.y == BB - 1
                            && wid == 7);

    // prologue: stage xs + B for chunk 0
    uint32_t dpack = stage_xs(sb, wid, lid, reB, imB, 0, edgeLowW, false);
    stage_b(sb, wid, lid, OFF_B0H, OFF_B0L, 0);
    CP_COMMIT();

    // MMA tile assignment: m-block (32 rows) = wid&3, n-half (48 cols) = wid>>2
    const int mBase = (wid & 3) * 32;
    const int nBase = (wid >> 2) * 48;
    const int rA    = (lid & 7) + ((lid >> 3) & 1) * 8;   // row within 16
    const int koffA = (lid >> 4) * 8;
    const int nB    = (lid & 7) + ((lid >> 4) << 3);
    const int kB    = ((lid >> 3) & 1) * 8;

    const float* xsw = smf + OFF_XS / 4 + wid * 8 * 76;

    float acc[2][6][4];
    #pragma unroll
    for (int mt = 0; mt < 2; mt++)
        #pragma unroll
        for (int nb = 0; nb < 6; nb++) {
            acc[mt][nb][0] = 0.f; acc[mt][nb][1] = 0.f;
            acc[mt][nb][2] = 0.f; acc[mt][nb][3] = 0.f;
        }

    for (int chunk = 0; chunk < NCHUNK; chunk++) {
        const int f0 = chunk * KC;
        const int wstart = (f0 == 0) ? 0 : f0 - 1;
        CP_WAIT0();
        __syncthreads();           // B buf + xs ready; prev MMA done

        // ---- Phase A: frame `wid`, f-pair (f0+2*lid, +1) -> A rows 16*wid.. ----
        const int fl = lid * 2;
        float v0[16], v1[16];
        {
            const int f = f0 + fl;
            if (f < FF) phaseA_s(xsw, dpack, wstart, f, v0);
            else        for (int c = 0; c < 16; c++) v0[c] = 0.f;
        }
        {
            const int f = f0 + fl + 1;
            if (f < FF) phaseA_s(xsw, dpack, wstart, f, v1);
            else        for (int c = 0; c < 16; c++) v1[c] = 0.f;
        }
        #pragma unroll
        for (int c = 0; c < 16; c++) {
            const int row = wid * 16 + c;
            __nv_bfloat162 h;
            h.x = __float2bfloat16(v0[c]); h.y = __float2bfloat16(v1[c]);
            *(__nv_bfloat162*)(smem + OFF_AH + row * 144 + fl * 2) = h;
            __nv_bfloat162 l;
            l.x = __float2bfloat16(v0[c] - __bfloat162float(h.x));
            l.y = __float2bfloat16(v1[c] - __bfloat162float(h.y));
            *(__nv_bfloat162*)(smem + OFF_AL + row * 144 + fl * 2) = l;
        }
        __syncthreads();           // all warps' A visible (cross-warp MMA tiles)

        // ---- prefetch next chunk (xs is warp-private; overlaps MMA below) ----
        if (chunk + 1 < NCHUNK) {
            const int f0n = f0 + KC;
            dpack = stage_xs(sb, wid, lid, reB, imB, f0n, false,
                             edgeHighW && (f0n == 7 * KC));
            if ((chunk + 1) & 1) stage_b(sb, wid, lid, OFF_B1H, OFF_B1L, f0n);
            else                 stage_b(sb, wid, lid, OFF_B0H, OFF_B0L, f0n);
        }
        CP_COMMIT();

        // ---- MMA: warp tile 32(m) x 48(n); 4 ks x 3 nbp x 2 mt x 3 products ----
        const uint32_t offBH = (chunk & 1) ? OFF_B1H : OFF_B0H;
        #pragma unroll
        for (int ks = 0; ks < 4; ks++) {
            const int k0 = ks * 16;
            uint32_t ah[2][4], al[2][4];
            #pragma unroll
            for (int mt = 0; mt < 2; mt++) {
                const uint32_t aA = sb + OFF_AH
                    + (mBase + mt * 16 + rA) * 144 + (k0 + koffA) * 2;
                LDSM4(ah[mt], aA);
                LDSM4(al[mt], aA + (OFF_AL - OFF_AH));
            }
            #pragma unroll
            for (int nbp = 0; nbp < 3; nbp++) {
                const uint32_t aB = sb + offBH
                    + (nBase + nbp * 16 + nB) * 144 + (k0 + kB) * 2;
                uint32_t bh[4], bl[4];
                LDSM4(bh, aB);
                LDSM4(bl, aB + (OFF_B0L - OFF_B0H));
                #pragma unroll
                for (int mt = 0; mt < 2; mt++) {
                    MMA16816(acc[mt][2*nbp],     ah[mt], bh[0], bh[1]);
                    MMA16816(acc[mt][2*nbp],     al[mt], bh[0], bh[1]);
                    MMA16816(acc[mt][2*nbp],     ah[mt], bl[0], bl[1]);
                    MMA16816(acc[mt][2*nbp + 1], ah[mt], bh[2], bh[3]);
                    MMA16816(acc[mt][2*nbp + 1], al[mt], bh[2], bh[3]);
                    MMA16816(acc[mt][2*nbp + 1], ah[mt], bl[2], bl[3]);
                }
            }
        }
    }
    __syncthreads();

    // accumulators -> Dsm [128 m][97 stride] (aliases A tiles)
    float* Dsm = smf + OFF_DSM / 4;
    {
        const int ncol = (lid & 3) * 2;
        #pragma unroll
        for (int mt = 0; mt < 2; mt++) {
            const int m0 = mBase + mt * 16 + (lid >> 2);
            #pragma unroll
            for (int nb = 0; nb < 6; nb++) {
                const int n0 = nBase + nb * 8 + ncol;
                Dsm[m0 * 97 + n0]           = acc[mt][nb][0];
                Dsm[m0 * 97 + n0 + 1]       = acc[mt][nb][1];
                Dsm[(m0 + 8) * 97 + n0]     = acc[mt][nb][2];
                Dsm[(m0 + 8) * 97 + n0 + 1] = acc[mt][nb][3];
            }
        }
    }
    __syncthreads();

    // Epilogue: reconstruct Hermitian bc, project with c2pv, scale, store
    if (tid < 192) {
        const int k = tid % KK, g = tid / KK, p0 = g * 4;
        const float invd = g_invds[k];
        for (int fr = 0; fr < FPC; fr++) {
            float sr[16], si[16];
            #pragma unroll
            for (int c = 0; c < 16; c++) {
                sr[c] = Dsm[(fr * 16 + c) * 97 + k];
                si[c] = Dsm[(fr * 16 + c) * 97 + 48 + k];
            }
            float br[16], bi[16];
            br[0]=sr[0];  bi[0]=si[0];   br[5]=sr[1];   bi[5]=si[1];
            br[10]=sr[4]; bi[10]=si[4];  br[15]=sr[5];  bi[15]=si[5];
            br[1]=sr[2]-si[3];    bi[1]=si[2]+sr[3];
            br[4]=sr[2]+si[3];    bi[4]=si[2]-sr[3];
            br[11]=sr[6]-si[7];   bi[11]=si[6]+sr[7];
            br[14]=sr[6]+si[7];   bi[14]=si[6]-sr[7];
            br[2]=sr[8]-si[9];    bi[2]=si[8]+sr[9];
            br[8]=sr[8]+si[9];    bi[8]=si[8]-sr[9];
            br[7]=sr[10]-si[11];  bi[7]=si[10]+sr[11];
            br[13]=sr[10]+si[11]; bi[13]=si[10]-sr[11];
            br[3]=sr[12]-si[13];  bi[3]=si[12]+sr[13];
            br[12]=sr[12]+si[13]; bi[12]=si[12]-sr[13];
            br[6]=sr[14]-si[15];  bi[6]=si[14]+sr[15];
            br[9]=sr[14]+si[15];  bi[9]=si[14]-sr[15];
            float a0=0.f, a1=0.f, a2=0.f, a3=0.f;
            #pragma unroll
            for (int c = 0; c < 16; c++) {
                const float vr = br[c], vi = bi[c];
                a0 = fmaf(c2s[(p0+0)*16+c], vr, a0); a0 = fmaf(-c2s[256+(p0+0)*16+c], vi, a0);
                a1 = fmaf(c2s[(p0+1)*16+c], vr, a1); a1 = fmaf(-c2s[256+(p0+1)*16+c], vi, a1);
                a2 = fmaf(c2s[(p0+2)*16+c], vr, a2); a2 = fmaf(-c2s[256+(p0+2)*16+c], vi, a2);
                a3 = fmaf(c2s[(p0+3)*16+c], vr, a3); a3 = fmaf(-c2s[256+(p0+3)*16+c], vi, a3);
            }
            float4 o = make_float4(a0*invd, a1*invd, a2*invd, a3*invd);
            *(float4*)(out + (((size_t)(b * KK + k)) * TT + (t0 + fr)) * 16 + p0) = o;
        }
    }
}

// ---------------------------------------------------------------------------
// IIR: 32 chunks of 32 frames, chunked parallel scan, in-place on out (B,K,T,16).
__global__ __launch_bounds__(512)
void pv_iir(float* __restrict__ out, const float* __restrict__ tau)
{
    __shared__ float Lend[512];
    __shared__ float Cin[512];
    const int chain = blockIdx.x;          // b*KK + k
    const int k = chain % KK;
    const int p = threadIdx.x & 15;
    const int c = threadIdx.x >> 4;        // chunk 0..31
    const float a = expf(-10.0f / tau[k]);
    const float bco = 1.0f - a;
    float* base = out + (size_t)chain * (TT * 16) + (size_t)c * 32 * 16 + p;

    float v[32];
    #pragma unroll
    for (int i = 0; i < 32; i++) v[i] = base[i * 16];
    float y = (c == 0) ? v[0] : bco * v[0];
    v[0] = y;
    #pragma unroll
    for (int i = 1; i < 32; i++) { y = fmaf(a, y, bco * v[i]); v[i] = y; }

    float A = a;
    #pragma unroll
    for (int s = 0; s < 5; s++) A *= A;    // a^32

    Lend[c * 16 + p] = y;
    __syncthreads();
    if (threadIdx.x < 16) {                 // one thread per p: serial over chunks
        float carry = 0.f;
        #pragma unroll
        for (int cc = 0; cc < 32; cc++) {
            Cin[cc * 16 + threadIdx.x] = carry;
            carry = Lend[cc * 16 + threadIdx.x] + A * carry;
        }
    }
    __syncthreads();
    const float carry = Cin[c * 16 + p];
    float pw = a;
    #pragma unroll
    for (int i = 0; i < 32; i++) { base[i * 16] = v[i] + pw * carry; pw *= a; }
}

// ---------------------------------------------------------------------------
extern "C" void kernel_launch(void* const* d_in, const int* in_sizes, int n_in,
                              void* d_out, int out_size)
{
    const float* bins_re = (const float*)d_in[0];
    const float* bins_im = (const float*)d_in[1];
    const float* band_re = (const float*)d_in[2];
    const float* band_im = (const float*)d_in[3];
    const float* c2pv_re = (const float*)d_in[4];
    const float* c2pv_im = (const float*)d_in[5];
    const float* tau     = (const float*)d_in[6];
    float* out = (float*)d_out;

    cudaFuncSetAttribute(pv_main, cudaFuncAttributeMaxDynamicSharedMemorySize,
                         SMEM_BYTES);

    pv_prep<<<240, 256>>>(band_re, band_im);

    dim3 grid(TT / FPC, BB);
    pv_main<<<grid, NTH, SMEM_BYTES>>>(bins_re, bins_im, c2pv_re, c2pv_im, out);

    pv_iir<<<BB * KK, 512>>>(out, tau);
}